// round 4
// baseline (speedup 1.0000x reference)
#include <cuda_runtime.h>
#include <math_constants.h>

#define N_NODES 50000
#define N_EDGES 1600000
#define IN_C 256
#define HID_C 128
#define OUT_C 16
#define HEADS 8
#define C1 16
#define NEG_SLOPE 0.2f

// ---------------- scratch (device globals; no allocation allowed) ----------------
__device__ __align__(16) float g_h1[N_NODES * HID_C];    // layer-1 transformed features
__device__ __align__(16) float g_h2[N_NODES * HID_C];    // layer-1 output (post bias+relu)
__device__ __align__(16) float g_g2[N_NODES * OUT_C];    // layer-2 transformed features
__device__ float g_asrc1[N_NODES * HEADS];
__device__ float g_adst1[N_NODES * HEADS];
__device__ float g_amax1[N_NODES * HEADS];
__device__ float g_asrc2[N_NODES];
__device__ float g_adst2[N_NODES];
__device__ float g_amax2[N_NODES];
__device__ int   g_deg[N_NODES];
__device__ int   g_rowptr[N_NODES + 1];
__device__ int   g_cursor[N_NODES];
__device__ int   g_adj[N_EDGES];

__device__ __forceinline__ float leaky(float a) {
    return (a > 0.f) ? a : NEG_SLOPE * a;
}

// ---------------- GEMM1: h1 = x @ W1  (M x 256) @ (256 x 128), packed f32x2 ----------------
#define BM 128
#define BN 128
#define BK 16
__global__ __launch_bounds__(256) void gemm1_kernel(const float* __restrict__ A,
                                                    const float* __restrict__ B, int M) {
    __shared__ __align__(16) float As[BK][BM + 8];   // stride 136 floats
    __shared__ __align__(16) float Bs[BK][BN];
    int tid = threadIdx.x;
    int bm = blockIdx.x * BM;
    int tx = tid & 15, ty = tid >> 4;
    unsigned long long acc2[8][4];   // 8 rows x 4 channel-pairs (f32x2)
#pragma unroll
    for (int i = 0; i < 8; i++)
#pragma unroll
        for (int j = 0; j < 4; j++) acc2[i][j] = 0ULL;

    for (int k0 = 0; k0 < IN_C; k0 += BK) {
        // load A tile (BM x BK), store transposed
#pragma unroll
        for (int i = 0; i < 2; i++) {
            int idx = tid + i * 256;
            int ar = idx >> 2;
            int ac = (idx & 3) * 4;
            float4 v = make_float4(0.f, 0.f, 0.f, 0.f);
            int grow = bm + ar;
            if (grow < M) v = *(const float4*)&A[grow * IN_C + k0 + ac];
            As[ac + 0][ar] = v.x;
            As[ac + 1][ar] = v.y;
            As[ac + 2][ar] = v.z;
            As[ac + 3][ar] = v.w;
        }
        // load B tile (BK x BN)
#pragma unroll
        for (int i = 0; i < 2; i++) {
            int idx = tid + i * 256;
            int br = idx >> 5;
            int bc = (idx & 31) * 4;
            *(float4*)&Bs[br][bc] = *(const float4*)&B[(k0 + br) * BN + bc];
        }
        __syncthreads();
#pragma unroll
        for (int k = 0; k < BK; k++) {
            float a[8];
            *(float4*)&a[0] = *(float4*)&As[k][ty * 8];
            *(float4*)&a[4] = *(float4*)&As[k][ty * 8 + 4];
            unsigned long long b2[4];
            {
                const ulonglong2* bp = (const ulonglong2*)&Bs[k][tx * 8];
                ulonglong2 bv0 = bp[0];
                ulonglong2 bv1 = bp[1];
                b2[0] = bv0.x; b2[1] = bv0.y; b2[2] = bv1.x; b2[3] = bv1.y;
            }
            unsigned long long ad[8];
#pragma unroll
            for (int i = 0; i < 8; i++)
                asm("mov.b64 %0, {%1, %1};" : "=l"(ad[i]) : "f"(a[i]));
#pragma unroll
            for (int i = 0; i < 8; i++)
#pragma unroll
                for (int j = 0; j < 4; j++)
                    asm("fma.rn.f32x2 %0, %1, %2, %3;"
                        : "=l"(acc2[i][j]) : "l"(ad[i]), "l"(b2[j]), "l"(acc2[i][j]));
        }
        __syncthreads();
    }
#pragma unroll
    for (int i = 0; i < 8; i++) {
        int grow = bm + ty * 8 + i;
        if (grow < M) {
            ulonglong2 s0, s1;
            s0.x = acc2[i][0]; s0.y = acc2[i][1];
            s1.x = acc2[i][2]; s1.y = acc2[i][3];
            *(ulonglong2*)&g_h1[grow * HID_C + tx * 8]     = s0;
            *(ulonglong2*)&g_h1[grow * HID_C + tx * 8 + 4] = s1;
        }
    }
}

// ---------------- attention coefficients, layer 1 ----------------
__global__ void attn1_kernel(const float* __restrict__ att_src,
                             const float* __restrict__ att_dst, int N) {
    int idx = blockIdx.x * blockDim.x + threadIdx.x;  // n*8 + h
    if (idx >= N * HEADS) return;
    int h = idx & 7;
    int n = idx >> 3;
    const float* hp = &g_h1[n * HID_C + h * C1];
    float ss = 0.f, sd = 0.f;
#pragma unroll
    for (int c = 0; c < C1; c++) {
        float v = hp[c];
        ss = fmaf(v, att_src[h * C1 + c], ss);
        sd = fmaf(v, att_dst[h * C1 + c], sd);
    }
    g_asrc1[idx] = ss;
    g_adst1[idx] = sd;
}

// ---------------- CSR build ----------------
__global__ void zero_deg_kernel(int N) {
    int i = blockIdx.x * blockDim.x + threadIdx.x;
    if (i < N) g_deg[i] = 0;
}

__global__ void count_kernel(const int* __restrict__ dst, int E) {
    int e = blockIdx.x * blockDim.x + threadIdx.x;
    if (e < E) atomicAdd(&g_deg[dst[e]], 1);
}

__global__ __launch_bounds__(1024) void scan_kernel(int N) {
    __shared__ int sums[1024];
    int t = threadIdx.x;
    int CH = (N + 1023) / 1024;
    int start = t * CH;
    int end = min(start + CH, N);
    int s = 0;
    for (int i = start; i < end; i++) s += g_deg[i];
    sums[t] = s;
    __syncthreads();
    for (int off = 1; off < 1024; off <<= 1) {
        int v = (t >= off) ? sums[t - off] : 0;
        __syncthreads();
        if (t >= off) sums[t] += v;
        __syncthreads();
    }
    int prefix = (t == 0) ? 0 : sums[t - 1];
    for (int i = start; i < end; i++) {
        g_rowptr[i] = prefix;
        g_cursor[i] = prefix;
        prefix += g_deg[i];
    }
    if (t == 1023) g_rowptr[N] = sums[1023];
}

__global__ void scatter_kernel(const int* __restrict__ src, const int* __restrict__ dst, int E) {
    int e = blockIdx.x * blockDim.x + threadIdx.x;
    if (e < E) {
        int d = dst[e];
        int pos = atomicAdd(&g_cursor[d], 1);
        g_adj[pos] = src[e];
    }
}

// ---------------- layer-1 max pass: amax1[n,h] = leaky(max(src scores) + adst) ----------------
__global__ __launch_bounds__(256) void maxpass1_kernel(int N) {
    int gw = (blockIdx.x * blockDim.x + threadIdx.x) >> 5;
    if (gw >= N) return;
    int lane = threadIdx.x & 31;
    int h = lane & 7;
    int g = lane >> 3;  // 4 edge groups
    int beg = g_rowptr[gw];
    int end = g_rowptr[gw + 1];
    float mx = -CUDART_INF_F;
    for (int e = beg + g; e < end; e += 4) {
        int src = g_adj[e];
        mx = fmaxf(mx, g_asrc1[src * HEADS + h]);
    }
    mx = fmaxf(mx, __shfl_xor_sync(0xffffffffu, mx, 8));
    mx = fmaxf(mx, __shfl_xor_sync(0xffffffffu, mx, 16));
    mx = fmaxf(mx, g_asrc1[gw * HEADS + h]);  // self loop
    float a = leaky(mx + g_adst1[gw * HEADS + h]);
    if (lane < 8) g_amax1[gw * HEADS + h] = a;
}

// ---------------- layer-1 aggregation: warp per node, single-exp weighted sum ----------------
__global__ __launch_bounds__(256) void agg1_kernel(const float* __restrict__ bias1, int N) {
    int gw = (blockIdx.x * blockDim.x + threadIdx.x) >> 5;
    if (gw >= N) return;
    int lane = threadIdx.x & 31;
    int head = lane >> 2;      // 4 lanes per head
    int c0 = lane * 4;         // this lane's 4 channels in [0,128)

    float adst = g_adst1[gw * HEADS + head];
    float amax = g_amax1[gw * HEADS + head];

    // self loop
    float p0 = __expf(leaky(g_asrc1[gw * HEADS + head] + adst) - amax);
    float s = p0;
    float4 hs = *(const float4*)&g_h1[gw * HID_C + c0];
    float4 acc = make_float4(p0 * hs.x, p0 * hs.y, p0 * hs.z, p0 * hs.w);

    int beg = g_rowptr[gw];
    int end = g_rowptr[gw + 1];
#pragma unroll 2
    for (int e = beg; e < end; e++) {
        int src = g_adj[e];
        float t = g_asrc1[src * HEADS + head];
        float p = __expf(leaky(t + adst) - amax);
        float4 hv = *(const float4*)&g_h1[src * HID_C + c0];
        s += p;
        acc.x = fmaf(p, hv.x, acc.x);
        acc.y = fmaf(p, hv.y, acc.y);
        acc.z = fmaf(p, hv.z, acc.z);
        acc.w = fmaf(p, hv.w, acc.w);
    }
    float inv = 1.f / s;
    float4 o;
    o.x = fmaxf(fmaf(acc.x, inv, bias1[c0 + 0]), 0.f);
    o.y = fmaxf(fmaf(acc.y, inv, bias1[c0 + 1]), 0.f);
    o.z = fmaxf(fmaf(acc.z, inv, bias1[c0 + 2]), 0.f);
    o.w = fmaxf(fmaf(acc.w, inv, bias1[c0 + 3]), 0.f);
    *(float4*)&g_h2[gw * HID_C + c0] = o;
}

// ---------------- layer 2: g2 = h2 @ W2 (+ attention scores), fused ----------------
__global__ __launch_bounds__(256) void gemm2_kernel(const float* __restrict__ W2,
                                                    const float* __restrict__ att_src,
                                                    const float* __restrict__ att_dst, int N) {
    __shared__ float Ws[HID_C * OUT_C];   // 128x16
    __shared__ float Hs[16][HID_C];       // 16 node rows
    int tid = threadIdx.x;
    int nodeBase = blockIdx.x * 16;
    for (int i = tid; i < HID_C * OUT_C; i += 256) Ws[i] = W2[i];
    int lnode = tid >> 4;
    int seg = tid & 15;
    int gnode = nodeBase + lnode;
    if (gnode < N) {
        *(float4*)&Hs[lnode][seg * 8]     = *(const float4*)&g_h2[gnode * HID_C + seg * 8];
        *(float4*)&Hs[lnode][seg * 8 + 4] = *(const float4*)&g_h2[gnode * HID_C + seg * 8 + 4];
    }
    __syncthreads();
    int j = tid & 15;
    float acc = 0.f;
#pragma unroll 8
    for (int c = 0; c < HID_C; c++) acc = fmaf(Hs[lnode][c], Ws[c * OUT_C + j], acc);
    float vs = acc * att_src[j];
    float vd = acc * att_dst[j];
#pragma unroll
    for (int off = 8; off; off >>= 1) {
        vs += __shfl_down_sync(0xffffffffu, vs, off, 16);
        vd += __shfl_down_sync(0xffffffffu, vd, off, 16);
    }
    if (gnode < N) {
        g_g2[gnode * OUT_C + j] = acc;
        if (j == 0) {
            g_asrc2[gnode] = vs;
            g_adst2[gnode] = vd;
        }
    }
}

// ---------------- layer-2 max pass ----------------
__global__ __launch_bounds__(256) void maxpass2_kernel(int N) {
    int gw = (blockIdx.x * blockDim.x + threadIdx.x) >> 5;
    if (gw >= N) return;
    int lane = threadIdx.x & 31;
    int beg = g_rowptr[gw];
    int end = g_rowptr[gw + 1];
    float mx = -CUDART_INF_F;
    for (int e = beg + lane; e < end; e += 32) {
        mx = fmaxf(mx, g_asrc2[g_adj[e]]);
    }
#pragma unroll
    for (int off = 16; off; off >>= 1)
        mx = fmaxf(mx, __shfl_xor_sync(0xffffffffu, mx, off));
    mx = fmaxf(mx, g_asrc2[gw]);  // self loop
    float a = leaky(mx + g_adst2[gw]);
    if (lane == 0) g_amax2[gw] = a;
}

// ---------------- layer-2 aggregation: warp per node, 2 edges/iter ----------------
__global__ __launch_bounds__(256) void agg2_kernel(const float* __restrict__ bias2,
                                                   float* __restrict__ out, int N) {
    int gw = (blockIdx.x * blockDim.x + threadIdx.x) >> 5;
    if (gw >= N) return;
    int lane = threadIdx.x & 31;
    int half = lane >> 4;
    int c = lane & 15;

    float adst = g_adst2[gw];
    float amax = g_amax2[gw];
    int beg = g_rowptr[gw];
    int end = g_rowptr[gw + 1];

    float s = 0.f, acc = 0.f;
    if (half == 0) {  // self loop in half 0
        float p0 = __expf(leaky(g_asrc2[gw] + adst) - amax);
        s = p0;
        acc = p0 * g_g2[gw * OUT_C + c];
    }
    for (int e = beg + half; e < end; e += 2) {
        int src = g_adj[e];
        float p = __expf(leaky(g_asrc2[src] + adst) - amax);
        s += p;
        acc = fmaf(p, g_g2[src * OUT_C + c], acc);
    }
    // merge the two halves
    s += __shfl_xor_sync(0xffffffffu, s, 16);
    acc += __shfl_xor_sync(0xffffffffu, acc, 16);
    if (half == 0) out[gw * OUT_C + c] = acc / s + bias2[c];
}

// ---------------- launch ----------------
extern "C" void kernel_launch(void* const* d_in, const int* in_sizes, int n_in,
                              void* d_out, int out_size) {
    const float* x        = (const float*)d_in[0];
    const int*   eidx     = (const int*)d_in[1];
    const float* W1       = (const float*)d_in[2];
    const float* att_src1 = (const float*)d_in[3];
    const float* att_dst1 = (const float*)d_in[4];
    const float* bias1    = (const float*)d_in[5];
    const float* W2       = (const float*)d_in[6];
    const float* att_src2 = (const float*)d_in[7];
    const float* att_dst2 = (const float*)d_in[8];
    const float* bias2    = (const float*)d_in[9];
    float* out = (float*)d_out;

    int N = in_sizes[0] / IN_C;
    int E = in_sizes[1] / 2;
    const int* srcArr = eidx;
    const int* dstArr = eidx + E;

    // GEMM1
    gemm1_kernel<<<(N + BM - 1) / BM, 256>>>(x, W1, N);
    // attention coefficients layer 1
    attn1_kernel<<<(N * HEADS + 255) / 256, 256>>>(att_src1, att_dst1, N);
    // CSR build
    zero_deg_kernel<<<(N + 255) / 256, 256>>>(N);
    count_kernel<<<(E + 255) / 256, 256>>>(dstArr, E);
    scan_kernel<<<1, 1024>>>(N);
    scatter_kernel<<<(E + 255) / 256, 256>>>(srcArr, dstArr, E);
    // layer-1 softmax max precompute + aggregation
    maxpass1_kernel<<<(N * 32 + 255) / 256, 256>>>(N);
    agg1_kernel<<<(N * 32 + 255) / 256, 256>>>(bias1, N);
    // layer 2 transform + attention scores
    gemm2_kernel<<<(N + 15) / 16, 256>>>(W2, att_src2, att_dst2, N);
    // layer-2 softmax max precompute + aggregation -> output
    maxpass2_kernel<<<(N * 32 + 255) / 256, 256>>>(N);
    agg2_kernel<<<(N * 32 + 255) / 256, 256>>>(bias2, out, N);
}

// round 5
// speedup vs baseline: 1.1034x; 1.1034x over previous
#include <cuda_runtime.h>
#include <cuda_fp16.h>
#include <math_constants.h>

#define N_NODES 50000
#define N_EDGES 1600000
#define IN_C 256
#define HID_C 128
#define OUT_C 16
#define HEADS 8
#define C1 16
#define NEG_SLOPE 0.2f

// ---------------- scratch (device globals; no allocation allowed) ----------------
__device__ __align__(16) float  g_h1[N_NODES * HID_C];    // layer-1 transformed features (fp32)
__device__ __align__(16) __half g_h1h[N_NODES * HID_C];   // fp16 copy for the edge gather
__device__ __align__(16) float  g_h2[N_NODES * HID_C];    // layer-1 output (post bias+relu)
__device__ __align__(16) float  g_g2[N_NODES * OUT_C];    // layer-2 transformed features
__device__ float g_asrc1[N_NODES * HEADS];
__device__ float g_adst1[N_NODES * HEADS];
__device__ float g_amax1[N_NODES * HEADS];
__device__ float g_asrc2[N_NODES];
__device__ float g_adst2[N_NODES];
__device__ float g_amax2[N_NODES];
__device__ int   g_deg[N_NODES];
__device__ int   g_rowptr[N_NODES + 1];
__device__ int   g_cursor[N_NODES];
__device__ int   g_adj[N_EDGES];

__device__ __forceinline__ float leaky(float a) {
    return (a > 0.f) ? a : NEG_SLOPE * a;
}

// ---------------- GEMM1: h1 = x @ W1  (M x 256) @ (256 x 128), packed f32x2 ----------------
#define BM 128
#define BN 128
#define BK 16
__global__ __launch_bounds__(256) void gemm1_kernel(const float* __restrict__ A,
                                                    const float* __restrict__ B, int M) {
    __shared__ __align__(16) float As[BK][BM + 8];   // stride 136 floats
    __shared__ __align__(16) float Bs[BK][BN];
    int tid = threadIdx.x;
    int bm = blockIdx.x * BM;
    int tx = tid & 15, ty = tid >> 4;
    unsigned long long acc2[8][4];   // 8 rows x 4 channel-pairs (f32x2)
#pragma unroll
    for (int i = 0; i < 8; i++)
#pragma unroll
        for (int j = 0; j < 4; j++) acc2[i][j] = 0ULL;

    for (int k0 = 0; k0 < IN_C; k0 += BK) {
#pragma unroll
        for (int i = 0; i < 2; i++) {
            int idx = tid + i * 256;
            int ar = idx >> 2;
            int ac = (idx & 3) * 4;
            float4 v = make_float4(0.f, 0.f, 0.f, 0.f);
            int grow = bm + ar;
            if (grow < M) v = *(const float4*)&A[grow * IN_C + k0 + ac];
            As[ac + 0][ar] = v.x;
            As[ac + 1][ar] = v.y;
            As[ac + 2][ar] = v.z;
            As[ac + 3][ar] = v.w;
        }
#pragma unroll
        for (int i = 0; i < 2; i++) {
            int idx = tid + i * 256;
            int br = idx >> 5;
            int bc = (idx & 31) * 4;
            *(float4*)&Bs[br][bc] = *(const float4*)&B[(k0 + br) * BN + bc];
        }
        __syncthreads();
#pragma unroll
        for (int k = 0; k < BK; k++) {
            float a[8];
            *(float4*)&a[0] = *(float4*)&As[k][ty * 8];
            *(float4*)&a[4] = *(float4*)&As[k][ty * 8 + 4];
            unsigned long long b2[4];
            {
                const ulonglong2* bp = (const ulonglong2*)&Bs[k][tx * 8];
                ulonglong2 bv0 = bp[0];
                ulonglong2 bv1 = bp[1];
                b2[0] = bv0.x; b2[1] = bv0.y; b2[2] = bv1.x; b2[3] = bv1.y;
            }
            unsigned long long ad[8];
#pragma unroll
            for (int i = 0; i < 8; i++)
                asm("mov.b64 %0, {%1, %1};" : "=l"(ad[i]) : "f"(a[i]));
#pragma unroll
            for (int i = 0; i < 8; i++)
#pragma unroll
                for (int j = 0; j < 4; j++)
                    asm("fma.rn.f32x2 %0, %1, %2, %3;"
                        : "=l"(acc2[i][j]) : "l"(ad[i]), "l"(b2[j]), "l"(acc2[i][j]));
        }
        __syncthreads();
    }
#pragma unroll
    for (int i = 0; i < 8; i++) {
        int grow = bm + ty * 8 + i;
        if (grow < M) {
            ulonglong2 s0, s1;
            s0.x = acc2[i][0]; s0.y = acc2[i][1];
            s1.x = acc2[i][2]; s1.y = acc2[i][3];
            *(ulonglong2*)&g_h1[grow * HID_C + tx * 8]     = s0;
            *(ulonglong2*)&g_h1[grow * HID_C + tx * 8 + 4] = s1;
        }
    }
}

// ---------------- attention coefficients, layer 1 (+ fp16 copy of h1) ----------------
__global__ void attn1_kernel(const float* __restrict__ att_src,
                             const float* __restrict__ att_dst, int N) {
    int idx = blockIdx.x * blockDim.x + threadIdx.x;  // n*8 + h
    if (idx >= N * HEADS) return;
    int h = idx & 7;
    int n = idx >> 3;
    const float* hp = &g_h1[n * HID_C + h * C1];
    float v[C1];
    float ss = 0.f, sd = 0.f;
#pragma unroll
    for (int c = 0; c < C1; c++) {
        v[c] = hp[c];
        ss = fmaf(v[c], att_src[h * C1 + c], ss);
        sd = fmaf(v[c], att_dst[h * C1 + c], sd);
    }
    g_asrc1[idx] = ss;
    g_adst1[idx] = sd;
    // fp16 copy for the gather path
    __half2* dst16 = (__half2*)&g_h1h[n * HID_C + h * C1];
#pragma unroll
    for (int c = 0; c < C1 / 2; c++)
        dst16[c] = __floats2half2_rn(v[2 * c], v[2 * c + 1]);
}

// ---------------- CSR build ----------------
__global__ void zero_deg_kernel(int N) {
    int i = blockIdx.x * blockDim.x + threadIdx.x;
    if (i < N) g_deg[i] = 0;
}

__global__ void count_kernel(const int* __restrict__ dst, int E) {
    int e = blockIdx.x * blockDim.x + threadIdx.x;
    if (e < E) atomicAdd(&g_deg[dst[e]], 1);
}

__global__ __launch_bounds__(1024) void scan_kernel(int N) {
    __shared__ int sums[1024];
    int t = threadIdx.x;
    int CH = (N + 1023) / 1024;
    int start = t * CH;
    int end = min(start + CH, N);
    int s = 0;
    for (int i = start; i < end; i++) s += g_deg[i];
    sums[t] = s;
    __syncthreads();
    for (int off = 1; off < 1024; off <<= 1) {
        int v = (t >= off) ? sums[t - off] : 0;
        __syncthreads();
        if (t >= off) sums[t] += v;
        __syncthreads();
    }
    int prefix = (t == 0) ? 0 : sums[t - 1];
    for (int i = start; i < end; i++) {
        g_rowptr[i] = prefix;
        g_cursor[i] = prefix;
        prefix += g_deg[i];
    }
    if (t == 1023) g_rowptr[N] = sums[1023];
}

__global__ void scatter_kernel(const int* __restrict__ src, const int* __restrict__ dst, int E) {
    int e = blockIdx.x * blockDim.x + threadIdx.x;
    if (e < E) {
        int d = dst[e];
        int pos = atomicAdd(&g_cursor[d], 1);
        g_adj[pos] = src[e];
    }
}

// ---------------- layer-1 max pass ----------------
__global__ __launch_bounds__(256) void maxpass1_kernel(int N) {
    int gw = (blockIdx.x * blockDim.x + threadIdx.x) >> 5;
    if (gw >= N) return;
    int lane = threadIdx.x & 31;
    int h = lane & 7;
    int g = lane >> 3;  // 4 edge groups
    int beg = g_rowptr[gw];
    int end = g_rowptr[gw + 1];
    float mx = -CUDART_INF_F;
    for (int e = beg + g; e < end; e += 4) {
        int src = g_adj[e];
        mx = fmaxf(mx, g_asrc1[src * HEADS + h]);
    }
    mx = fmaxf(mx, __shfl_xor_sync(0xffffffffu, mx, 8));
    mx = fmaxf(mx, __shfl_xor_sync(0xffffffffu, mx, 16));
    mx = fmaxf(mx, g_asrc1[gw * HEADS + h]);  // self loop
    float a = leaky(mx + g_adst1[gw * HEADS + h]);
    if (lane < 8) g_amax1[gw * HEADS + h] = a;
}

// ---------------- layer-1 aggregation: warp per node, fp16 gather ----------------
__global__ __launch_bounds__(256) void agg1_kernel(const float* __restrict__ bias1, int N) {
    int gw = (blockIdx.x * blockDim.x + threadIdx.x) >> 5;
    if (gw >= N) return;
    int lane = threadIdx.x & 31;
    int head = lane >> 2;      // 4 lanes per head
    int c0 = lane * 4;         // this lane's 4 channels in [0,128)

    float adst = g_adst1[gw * HEADS + head];
    float amax = g_amax1[gw * HEADS + head];

    // self loop
    float p0 = __expf(leaky(g_asrc1[gw * HEADS + head] + adst) - amax);
    float s = p0;
    float4 acc;
    {
        uint2 hraw = *(const uint2*)&g_h1h[gw * HID_C + c0];
        float2 f01 = __half22float2(*(__half2*)&hraw.x);
        float2 f23 = __half22float2(*(__half2*)&hraw.y);
        acc = make_float4(p0 * f01.x, p0 * f01.y, p0 * f23.x, p0 * f23.y);
    }

    int beg = g_rowptr[gw];
    int end = g_rowptr[gw + 1];
#pragma unroll 4
    for (int e = beg; e < end; e++) {
        int src = g_adj[e];
        float t = g_asrc1[src * HEADS + head];
        uint2 hraw = *(const uint2*)&g_h1h[src * HID_C + c0];
        float p = __expf(leaky(t + adst) - amax);
        float2 f01 = __half22float2(*(__half2*)&hraw.x);
        float2 f23 = __half22float2(*(__half2*)&hraw.y);
        s += p;
        acc.x = fmaf(p, f01.x, acc.x);
        acc.y = fmaf(p, f01.y, acc.y);
        acc.z = fmaf(p, f23.x, acc.z);
        acc.w = fmaf(p, f23.y, acc.w);
    }
    float inv = 1.f / s;
    float4 o;
    o.x = fmaxf(fmaf(acc.x, inv, bias1[c0 + 0]), 0.f);
    o.y = fmaxf(fmaf(acc.y, inv, bias1[c0 + 1]), 0.f);
    o.z = fmaxf(fmaf(acc.z, inv, bias1[c0 + 2]), 0.f);
    o.w = fmaxf(fmaf(acc.w, inv, bias1[c0 + 3]), 0.f);
    *(float4*)&g_h2[gw * HID_C + c0] = o;
}

// ---------------- layer 2: g2 = h2 @ W2 (+ attention scores), fused ----------------
__global__ __launch_bounds__(256) void gemm2_kernel(const float* __restrict__ W2,
                                                    const float* __restrict__ att_src,
                                                    const float* __restrict__ att_dst, int N) {
    __shared__ float Ws[HID_C * OUT_C];   // 128x16
    __shared__ float Hs[16][HID_C];       // 16 node rows
    int tid = threadIdx.x;
    int nodeBase = blockIdx.x * 16;
    for (int i = tid; i < HID_C * OUT_C; i += 256) Ws[i] = W2[i];
    int lnode = tid >> 4;
    int seg = tid & 15;
    int gnode = nodeBase + lnode;
    if (gnode < N) {
        *(float4*)&Hs[lnode][seg * 8]     = *(const float4*)&g_h2[gnode * HID_C + seg * 8];
        *(float4*)&Hs[lnode][seg * 8 + 4] = *(const float4*)&g_h2[gnode * HID_C + seg * 8 + 4];
    }
    __syncthreads();
    int j = tid & 15;
    float acc = 0.f;
#pragma unroll 8
    for (int c = 0; c < HID_C; c++) acc = fmaf(Hs[lnode][c], Ws[c * OUT_C + j], acc);
    float vs = acc * att_src[j];
    float vd = acc * att_dst[j];
#pragma unroll
    for (int off = 8; off; off >>= 1) {
        vs += __shfl_down_sync(0xffffffffu, vs, off, 16);
        vd += __shfl_down_sync(0xffffffffu, vd, off, 16);
    }
    if (gnode < N) {
        g_g2[gnode * OUT_C + j] = acc;
        if (j == 0) {
            g_asrc2[gnode] = vs;
            g_adst2[gnode] = vd;
        }
    }
}

// ---------------- layer-2 max pass ----------------
__global__ __launch_bounds__(256) void maxpass2_kernel(int N) {
    int gw = (blockIdx.x * blockDim.x + threadIdx.x) >> 5;
    if (gw >= N) return;
    int lane = threadIdx.x & 31;
    int beg = g_rowptr[gw];
    int end = g_rowptr[gw + 1];
    float mx = -CUDART_INF_F;
    for (int e = beg + lane; e < end; e += 32) {
        mx = fmaxf(mx, g_asrc2[g_adj[e]]);
    }
#pragma unroll
    for (int off = 16; off; off >>= 1)
        mx = fmaxf(mx, __shfl_xor_sync(0xffffffffu, mx, off));
    mx = fmaxf(mx, g_asrc2[gw]);  // self loop
    float a = leaky(mx + g_adst2[gw]);
    if (lane == 0) g_amax2[gw] = a;
}

// ---------------- layer-2 aggregation ----------------
__global__ __launch_bounds__(256) void agg2_kernel(const float* __restrict__ bias2,
                                                   float* __restrict__ out, int N) {
    int gw = (blockIdx.x * blockDim.x + threadIdx.x) >> 5;
    if (gw >= N) return;
    int lane = threadIdx.x & 31;
    int half = lane >> 4;
    int c = lane & 15;

    float adst = g_adst2[gw];
    float amax = g_amax2[gw];
    int beg = g_rowptr[gw];
    int end = g_rowptr[gw + 1];

    float s = 0.f, acc = 0.f;
    if (half == 0) {  // self loop in half 0
        float p0 = __expf(leaky(g_asrc2[gw] + adst) - amax);
        s = p0;
        acc = p0 * g_g2[gw * OUT_C + c];
    }
#pragma unroll 2
    for (int e = beg + half; e < end; e += 2) {
        int src = g_adj[e];
        float p = __expf(leaky(g_asrc2[src] + adst) - amax);
        s += p;
        acc = fmaf(p, g_g2[src * OUT_C + c], acc);
    }
    s += __shfl_xor_sync(0xffffffffu, s, 16);
    acc += __shfl_xor_sync(0xffffffffu, acc, 16);
    if (half == 0) out[gw * OUT_C + c] = acc / s + bias2[c];
}

// ---------------- launch: fork-join graph (CSR build || GEMM1->attn1) ----------------
extern "C" void kernel_launch(void* const* d_in, const int* in_sizes, int n_in,
                              void* d_out, int out_size) {
    const float* x        = (const float*)d_in[0];
    const int*   eidx     = (const int*)d_in[1];
    const float* W1       = (const float*)d_in[2];
    const float* att_src1 = (const float*)d_in[3];
    const float* att_dst1 = (const float*)d_in[4];
    const float* bias1    = (const float*)d_in[5];
    const float* W2       = (const float*)d_in[6];
    const float* att_src2 = (const float*)d_in[7];
    const float* att_dst2 = (const float*)d_in[8];
    const float* bias2    = (const float*)d_in[9];
    float* out = (float*)d_out;

    int N = in_sizes[0] / IN_C;
    int E = in_sizes[1] / 2;
    const int* srcArr = eidx;
    const int* dstArr = eidx + E;

    // lazily-created side stream + events (created on the first, non-captured,
    // correctness call; only reused afterwards — no resource churn per launch)
    static cudaStream_t s2 = nullptr;
    static cudaEvent_t evFork = nullptr, evJoin = nullptr;
    if (!s2) {
        cudaStreamCreateWithFlags(&s2, cudaStreamNonBlocking);
        cudaEventCreateWithFlags(&evFork, cudaEventDisableTiming);
        cudaEventCreateWithFlags(&evJoin, cudaEventDisableTiming);
    }

    // fork: CSR build on side stream
    cudaEventRecord(evFork, 0);
    cudaStreamWaitEvent(s2, evFork, 0);
    zero_deg_kernel<<<(N + 255) / 256, 256, 0, s2>>>(N);
    count_kernel<<<(E + 255) / 256, 256, 0, s2>>>(dstArr, E);
    scan_kernel<<<1, 1024, 0, s2>>>(N);
    scatter_kernel<<<(E + 255) / 256, 256, 0, s2>>>(srcArr, dstArr, E);
    cudaEventRecord(evJoin, s2);

    // main stream: dense transform
    gemm1_kernel<<<(N + BM - 1) / BM, 256>>>(x, W1, N);
    attn1_kernel<<<(N * HEADS + 255) / 256, 256>>>(att_src1, att_dst1, N);

    // join: everything below needs both branches
    cudaStreamWaitEvent(0, evJoin, 0);

    maxpass1_kernel<<<(N * 32 + 255) / 256, 256>>>(N);
    agg1_kernel<<<(N * 32 + 255) / 256, 256>>>(bias1, N);
    gemm2_kernel<<<(N + 15) / 16, 256>>>(W2, att_src2, att_dst2, N);
    maxpass2_kernel<<<(N * 32 + 255) / 256, 256>>>(N);
    agg2_kernel<<<(N * 32 + 255) / 256, 256>>>(bias2, out, N);
}

// round 6
// speedup vs baseline: 1.2371x; 1.1212x over previous
#include <cuda_runtime.h>
#include <cuda_fp16.h>
#include <math_constants.h>

#define N_NODES 50000
#define N_EDGES 1600000
#define IN_C 256
#define HID_C 128
#define OUT_C 16
#define HEADS 8
#define C1 16
#define NEG_SLOPE 0.2f

// ---------------- scratch (device globals; no allocation allowed) ----------------
__device__ __align__(16) __half g_h1h[N_NODES * HID_C];   // layer-1 features, fp16 (gather payload)
__device__ __align__(16) float  g_h2[N_NODES * HID_C];    // layer-1 output (post bias+relu)
__device__ __align__(16) float  g_g2[N_NODES * OUT_C];    // layer-2 transformed features
__device__ float g_asrc1[N_NODES * HEADS];
__device__ float g_adst1[N_NODES * HEADS];
__device__ float g_asrc2[N_NODES];
__device__ float g_adst2[N_NODES];
__device__ int   g_deg[N_NODES];
__device__ int   g_rowptr[N_NODES + 1];
__device__ int   g_cursor[N_NODES];
__device__ int   g_adj[N_EDGES];

__device__ __forceinline__ float leaky(float a) {
    return (a > 0.f) ? a : NEG_SLOPE * a;
}

// ---------------- GEMM1 + fused attn coefficients + fp16 store ----------------
// h1 = x @ W1 (M x 256)(256 x 128); writes g_h1h (fp16), g_asrc1, g_adst1.
#define BM 128
#define BN 128
#define BK 16
__global__ __launch_bounds__(256) void gemm1_kernel(const float* __restrict__ A,
                                                    const float* __restrict__ B,
                                                    const float* __restrict__ att_src,
                                                    const float* __restrict__ att_dst, int M) {
    __shared__ __align__(16) float As[BK][BM + 8];   // stride 136 floats
    __shared__ __align__(16) float Bs[BK][BN];
    int tid = threadIdx.x;
    int bm = blockIdx.x * BM;
    int tx = tid & 15, ty = tid >> 4;
    unsigned long long acc2[8][4];   // 8 rows x 4 channel-pairs (f32x2)
#pragma unroll
    for (int i = 0; i < 8; i++)
#pragma unroll
        for (int j = 0; j < 4; j++) acc2[i][j] = 0ULL;

    for (int k0 = 0; k0 < IN_C; k0 += BK) {
#pragma unroll
        for (int i = 0; i < 2; i++) {
            int idx = tid + i * 256;
            int ar = idx >> 2;
            int ac = (idx & 3) * 4;
            float4 v = make_float4(0.f, 0.f, 0.f, 0.f);
            int grow = bm + ar;
            if (grow < M) v = *(const float4*)&A[grow * IN_C + k0 + ac];
            As[ac + 0][ar] = v.x;
            As[ac + 1][ar] = v.y;
            As[ac + 2][ar] = v.z;
            As[ac + 3][ar] = v.w;
        }
#pragma unroll
        for (int i = 0; i < 2; i++) {
            int idx = tid + i * 256;
            int br = idx >> 5;
            int bc = (idx & 31) * 4;
            *(float4*)&Bs[br][bc] = *(const float4*)&B[(k0 + br) * BN + bc];
        }
        __syncthreads();
#pragma unroll
        for (int k = 0; k < BK; k++) {
            float a[8];
            *(float4*)&a[0] = *(float4*)&As[k][ty * 8];
            *(float4*)&a[4] = *(float4*)&As[k][ty * 8 + 4];
            unsigned long long b2[4];
            {
                const ulonglong2* bp = (const ulonglong2*)&Bs[k][tx * 8];
                ulonglong2 bv0 = bp[0];
                ulonglong2 bv1 = bp[1];
                b2[0] = bv0.x; b2[1] = bv0.y; b2[2] = bv1.x; b2[3] = bv1.y;
            }
            unsigned long long ad[8];
#pragma unroll
            for (int i = 0; i < 8; i++)
                asm("mov.b64 %0, {%1, %1};" : "=l"(ad[i]) : "f"(a[i]));
#pragma unroll
            for (int i = 0; i < 8; i++)
#pragma unroll
                for (int j = 0; j < 4; j++)
                    asm("fma.rn.f32x2 %0, %1, %2, %3;"
                        : "=l"(acc2[i][j]) : "l"(ad[i]), "l"(b2[j]), "l"(acc2[i][j]));
        }
        __syncthreads();
    }

    // epilogue: fp16 store + fused attention-coefficient dots
    int head = tx >> 1;                 // this thread-pair's head
    float as_v[8], ad_v[8];             // att vectors for this thread's 8 channels
#pragma unroll
    for (int j = 0; j < 8; j++) {
        as_v[j] = att_src[tx * 8 + j];
        ad_v[j] = att_dst[tx * 8 + j];
    }
#pragma unroll
    for (int i = 0; i < 8; i++) {
        int grow = bm + ty * 8 + i;
        float v[8];
#pragma unroll
        for (int j = 0; j < 4; j++)
            asm("mov.b64 {%0, %1}, %2;" : "=f"(v[2 * j]), "=f"(v[2 * j + 1]) : "l"(acc2[i][j]));
        float ss = 0.f, sd = 0.f;
#pragma unroll
        for (int j = 0; j < 8; j++) {
            ss = fmaf(v[j], as_v[j], ss);
            sd = fmaf(v[j], ad_v[j], sd);
        }
        ss += __shfl_xor_sync(0xffffffffu, ss, 1);
        sd += __shfl_xor_sync(0xffffffffu, sd, 1);
        if (grow < M) {
            uint2 h16;
            {
                __half2 p0 = __floats2half2_rn(v[0], v[1]);
                __half2 p1 = __floats2half2_rn(v[2], v[3]);
                h16.x = *(unsigned*)&p0 ;
                h16.y = 0;
                unsigned u1 = *(unsigned*)&p1;
                h16.y = u1;
            }
            uint2 h16b;
            {
                __half2 p2 = __floats2half2_rn(v[4], v[5]);
                __half2 p3 = __floats2half2_rn(v[6], v[7]);
                h16b.x = *(unsigned*)&p2;
                h16b.y = *(unsigned*)&p3;
            }
            uint4 st;
            st.x = h16.x; st.y = h16.y; st.z = h16b.x; st.w = h16b.y;
            *(uint4*)&g_h1h[grow * HID_C + tx * 8] = st;
            if ((tx & 1) == 0) {
                g_asrc1[grow * HEADS + head] = ss;
                g_adst1[grow * HEADS + head] = sd;
            }
        }
    }
}

// ---------------- CSR build (4 edges / thread) ----------------
__global__ void count_kernel(const int* __restrict__ dst, int E) {
    int base = (blockIdx.x * blockDim.x + threadIdx.x) * 4;
    if (base + 3 < E) {
        int4 d = *(const int4*)&dst[base];
        atomicAdd(&g_deg[d.x], 1);
        atomicAdd(&g_deg[d.y], 1);
        atomicAdd(&g_deg[d.z], 1);
        atomicAdd(&g_deg[d.w], 1);
    } else {
        for (int e = base; e < E; e++) atomicAdd(&g_deg[dst[e]], 1);
    }
}

__global__ __launch_bounds__(1024) void scan_kernel(int N) {
    __shared__ int sums[1024];
    int t = threadIdx.x;
    int CH = (N + 1023) / 1024;
    int start = t * CH;
    int end = min(start + CH, N);
    int s = 0;
    for (int i = start; i < end; i++) s += g_deg[i];
    sums[t] = s;
    __syncthreads();
    for (int off = 1; off < 1024; off <<= 1) {
        int v = (t >= off) ? sums[t - off] : 0;
        __syncthreads();
        if (t >= off) sums[t] += v;
        __syncthreads();
    }
    int prefix = (t == 0) ? 0 : sums[t - 1];
    for (int i = start; i < end; i++) {
        g_rowptr[i] = prefix;
        g_cursor[i] = prefix;
        prefix += g_deg[i];
    }
    if (t == 1023) g_rowptr[N] = sums[1023];
}

__global__ void scatter_kernel(const int* __restrict__ src, const int* __restrict__ dst, int E) {
    int base = (blockIdx.x * blockDim.x + threadIdx.x) * 4;
    if (base + 3 < E) {
        int4 d = *(const int4*)&dst[base];
        int4 sv = *(const int4*)&src[base];
        int p0 = atomicAdd(&g_cursor[d.x], 1);
        int p1 = atomicAdd(&g_cursor[d.y], 1);
        int p2 = atomicAdd(&g_cursor[d.z], 1);
        int p3 = atomicAdd(&g_cursor[d.w], 1);
        g_adj[p0] = sv.x;
        g_adj[p1] = sv.y;
        g_adj[p2] = sv.z;
        g_adj[p3] = sv.w;
    } else {
        for (int e = base; e < E; e++) {
            int pos = atomicAdd(&g_cursor[dst[e]], 1);
            g_adj[pos] = src[e];
        }
    }
}

// ---------------- layer-1 aggregation: warp per node, fp16 gather, no max pass ----------------
__global__ __launch_bounds__(256) void agg1_kernel(const float* __restrict__ bias1, int N) {
    int gw = (blockIdx.x * blockDim.x + threadIdx.x) >> 5;
    if (gw >= N) return;
    int lane = threadIdx.x & 31;
    int head = lane >> 2;      // 4 lanes per head
    int c0 = lane * 4;         // this lane's 4 channels in [0,128)

    float adst = g_adst1[gw * HEADS + head];

    // self loop
    float p0 = __expf(leaky(g_asrc1[gw * HEADS + head] + adst));
    float s = p0;
    float4 acc;
    {
        uint2 hraw = *(const uint2*)&g_h1h[gw * HID_C + c0];
        float2 f01 = __half22float2(*(__half2*)&hraw.x);
        float2 f23 = __half22float2(*(__half2*)&hraw.y);
        acc = make_float4(p0 * f01.x, p0 * f01.y, p0 * f23.x, p0 * f23.y);
    }

    int beg = g_rowptr[gw];
    int end = g_rowptr[gw + 1];
#pragma unroll 4
    for (int e = beg; e < end; e++) {
        int src = g_adj[e];
        float t = g_asrc1[src * HEADS + head];
        uint2 hraw = *(const uint2*)&g_h1h[src * HID_C + c0];
        float p = __expf(leaky(t + adst));
        float2 f01 = __half22float2(*(__half2*)&hraw.x);
        float2 f23 = __half22float2(*(__half2*)&hraw.y);
        s += p;
        acc.x = fmaf(p, f01.x, acc.x);
        acc.y = fmaf(p, f01.y, acc.y);
        acc.z = fmaf(p, f23.x, acc.z);
        acc.w = fmaf(p, f23.y, acc.w);
    }
    float inv = 1.f / s;
    float4 o;
    o.x = fmaxf(fmaf(acc.x, inv, bias1[c0 + 0]), 0.f);
    o.y = fmaxf(fmaf(acc.y, inv, bias1[c0 + 1]), 0.f);
    o.z = fmaxf(fmaf(acc.z, inv, bias1[c0 + 2]), 0.f);
    o.w = fmaxf(fmaf(acc.w, inv, bias1[c0 + 3]), 0.f);
    *(float4*)&g_h2[gw * HID_C + c0] = o;
}

// ---------------- layer 2: g2 = h2 @ W2 (+ attention scores), fused ----------------
__global__ __launch_bounds__(256) void gemm2_kernel(const float* __restrict__ W2,
                                                    const float* __restrict__ att_src,
                                                    const float* __restrict__ att_dst, int N) {
    __shared__ float Ws[HID_C * OUT_C];   // 128x16
    __shared__ float Hs[16][HID_C];       // 16 node rows
    int tid = threadIdx.x;
    int nodeBase = blockIdx.x * 16;
    for (int i = tid; i < HID_C * OUT_C; i += 256) Ws[i] = W2[i];
    int lnode = tid >> 4;
    int seg = tid & 15;
    int gnode = nodeBase + lnode;
    if (gnode < N) {
        *(float4*)&Hs[lnode][seg * 8]     = *(const float4*)&g_h2[gnode * HID_C + seg * 8];
        *(float4*)&Hs[lnode][seg * 8 + 4] = *(const float4*)&g_h2[gnode * HID_C + seg * 8 + 4];
    }
    __syncthreads();
    int j = tid & 15;
    float acc = 0.f;
#pragma unroll 8
    for (int c = 0; c < HID_C; c++) acc = fmaf(Hs[lnode][c], Ws[c * OUT_C + j], acc);
    float vs = acc * att_src[j];
    float vd = acc * att_dst[j];
#pragma unroll
    for (int off = 8; off; off >>= 1) {
        vs += __shfl_down_sync(0xffffffffu, vs, off, 16);
        vd += __shfl_down_sync(0xffffffffu, vd, off, 16);
    }
    if (gnode < N) {
        g_g2[gnode * OUT_C + j] = acc;
        if (j == 0) {
            g_asrc2[gnode] = vs;
            g_adst2[gnode] = vd;
        }
    }
}

// ---------------- layer-2 aggregation (no max pass) ----------------
__global__ __launch_bounds__(256) void agg2_kernel(const float* __restrict__ bias2,
                                                   float* __restrict__ out, int N) {
    int gw = (blockIdx.x * blockDim.x + threadIdx.x) >> 5;
    if (gw >= N) return;
    int lane = threadIdx.x & 31;
    int half = lane >> 4;
    int c = lane & 15;

    float adst = g_adst2[gw];
    int beg = g_rowptr[gw];
    int end = g_rowptr[gw + 1];

    float s = 0.f, acc = 0.f;
    if (half == 0) {  // self loop in half 0
        float p0 = __expf(leaky(g_asrc2[gw] + adst));
        s = p0;
        acc = p0 * g_g2[gw * OUT_C + c];
    }
#pragma unroll 2
    for (int e = beg + half; e < end; e += 2) {
        int src = g_adj[e];
        float p = __expf(leaky(g_asrc2[src] + adst));
        s += p;
        acc = fmaf(p, g_g2[src * OUT_C + c], acc);
    }
    s += __shfl_xor_sync(0xffffffffu, s, 16);
    acc += __shfl_xor_sync(0xffffffffu, acc, 16);
    if (half == 0) out[gw * OUT_C + c] = acc / s + bias2[c];
}

// ---------------- launch: fork-join graph (CSR build || fused GEMM1) ----------------
extern "C" void kernel_launch(void* const* d_in, const int* in_sizes, int n_in,
                              void* d_out, int out_size) {
    const float* x        = (const float*)d_in[0];
    const int*   eidx     = (const int*)d_in[1];
    const float* W1       = (const float*)d_in[2];
    const float* att_src1 = (const float*)d_in[3];
    const float* att_dst1 = (const float*)d_in[4];
    const float* bias1    = (const float*)d_in[5];
    const float* W2       = (const float*)d_in[6];
    const float* att_src2 = (const float*)d_in[7];
    const float* att_dst2 = (const float*)d_in[8];
    const float* bias2    = (const float*)d_in[9];
    float* out = (float*)d_out;

    int N = in_sizes[0] / IN_C;
    int E = in_sizes[1] / 2;
    const int* srcArr = eidx;
    const int* dstArr = eidx + E;

    // lazily-created side stream + events + symbol address (first call is the
    // non-captured correctness run; reused afterwards)
    static cudaStream_t s2 = nullptr;
    static cudaEvent_t evFork = nullptr, evJoin = nullptr;
    static void* degPtr = nullptr;
    if (!s2) {
        cudaStreamCreateWithFlags(&s2, cudaStreamNonBlocking);
        cudaEventCreateWithFlags(&evFork, cudaEventDisableTiming);
        cudaEventCreateWithFlags(&evJoin, cudaEventDisableTiming);
        cudaGetSymbolAddress(&degPtr, g_deg);
    }

    // fork: CSR build on side stream
    cudaEventRecord(evFork, 0);
    cudaStreamWaitEvent(s2, evFork, 0);
    cudaMemsetAsync(degPtr, 0, N_NODES * sizeof(int), s2);
    count_kernel<<<(E / 4 + 255) / 256, 256, 0, s2>>>(dstArr, E);
    scan_kernel<<<1, 1024, 0, s2>>>(N);
    scatter_kernel<<<(E / 4 + 255) / 256, 256, 0, s2>>>(srcArr, dstArr, E);
    cudaEventRecord(evJoin, s2);

    // main stream: dense transform (attn coefficients fused into epilogue)
    gemm1_kernel<<<(N + BM - 1) / BM, 256>>>(x, W1, att_src1, att_dst1, N);

    // join: everything below needs both branches
    cudaStreamWaitEvent(0, evJoin, 0);

    agg1_kernel<<<(N * 32 + 255) / 256, 256>>>(bias1, N);
    gemm2_kernel<<<(N + 15) / 16, 256>>>(W2, att_src2, att_dst2, N);
    agg2_kernel<<<(N * 32 + 255) / 256, 256>>>(bias2, out, N);
}

// round 8
// speedup vs baseline: 1.8647x; 1.5073x over previous
#include <cuda_runtime.h>
#include <cuda_fp16.h>
#include <math_constants.h>
#include <cstdint>

#define N_NODES 50000
#define N_EDGES 1600000
#define IN_C 256
#define HID_C 128
#define OUT_C 16
#define HEADS 8
#define NEG_SLOPE 0.2f

#define N_PAD 53248              // 52 * 1024, for the vectorized scan

// ---------------- scratch (device globals; no allocation allowed) ----------------
__device__ __align__(16) __half g_h1h[N_NODES * HID_C];   // layer-1 features fp16 (gather payload)
__device__ __align__(16) float  g_h2[N_NODES * HID_C];    // layer-1 output (post bias+relu)
__device__ __align__(16) __half g_g2h[N_NODES * OUT_C];   // layer-2 features fp16 (gather payload)
__device__ __align__(16) uint2  g_Bfrag[16 * 16 * 32];    // W1 in mma B-fragment layout (64KB)
__device__ float g_asrc1[N_NODES * HEADS];
__device__ float g_adst1[N_NODES * HEADS];
__device__ float g_asrc2[N_NODES];
__device__ float g_adst2[N_NODES];
__device__ int   g_deg[N_PAD];
__device__ int   g_rowptr[N_PAD + 8];
__device__ int   g_cursor[N_PAD + 8];
__device__ int   g_adj[N_EDGES];

__device__ __forceinline__ float leaky(float a) { return (a > 0.f) ? a : NEG_SLOPE * a; }

__device__ __forceinline__ uint32_t smem_u32(const void* p) {
    uint32_t a;
    asm("{ .reg .u64 t; cvta.to.shared.u64 t, %1; cvt.u32.u64 %0, t; }" : "=r"(a) : "l"(p));
    return a;
}

// ---------------- W1 -> mma B-fragment layout (runs once per call, tiny) ----------------
// m16n8k16 .row.col B fragment: lane l, reg r hold half2 {B[k][n], B[k+1][n]},
// k = kstep*16 + r*8 + (l&3)*2, n = ntile*8 + (l>>2).
__global__ void prep_bfrag_kernel(const float* __restrict__ W1) {
    int idx = blockIdx.x * blockDim.x + threadIdx.x;   // 8192
    int lane = idx & 31;
    int ntile = (idx >> 5) & 15;
    int kstep = idx >> 9;
    int n = ntile * 8 + (lane >> 2);
    int k0 = kstep * 16 + (lane & 3) * 2;
    __half2 b0 = __floats2half2_rn(W1[k0 * HID_C + n],       W1[(k0 + 1) * HID_C + n]);
    __half2 b1 = __floats2half2_rn(W1[(k0 + 8) * HID_C + n], W1[(k0 + 9) * HID_C + n]);
    uint2 v;
    v.x = *(uint32_t*)&b0;
    v.y = *(uint32_t*)&b1;
    g_Bfrag[idx] = v;
}

// ---------------- GEMM1 via mma.sync (HMMA): h1h = fp16(x @ W1) ----------------
// CTA: 256 thr = 8 warps (2m x 4n). CTA tile 128x128, warp tile 64x32, K chunked by 32.
#define ASTRIDE 40   // halves; 80B row stride -> conflict-free ldmatrix
__global__ __launch_bounds__(256, 2) void gemm1_mma_kernel(const float* __restrict__ A, int M) {
    __shared__ __align__(16) __half As[128][ASTRIDE];
    int tid = threadIdx.x, wid = tid >> 5, lane = tid & 31;
    int warp_m = wid >> 2, warp_n = wid & 3;
    int bm = blockIdx.x * 128;

    float acc[4][4][4];
#pragma unroll
    for (int mt = 0; mt < 4; mt++)
#pragma unroll
        for (int nt = 0; nt < 4; nt++)
#pragma unroll
            for (int r = 0; r < 4; r++) acc[mt][nt][r] = 0.f;

    // per-thread ldmatrix base: row = warp_m*64 + (lane&15), col = (lane>>4)*8
    uint32_t aBase = smem_u32(&As[0][0]) +
                     ((uint32_t)((warp_m * 64 + (lane & 15)) * ASTRIDE + (lane >> 4) * 8) << 1);

    // A-load mapping: row = tid>>1, col block = (tid&1)*16
    int lr = tid >> 1;
    int lc = (tid & 1) * 16;
    int grow_l = bm + lr;
    const float4* arow = (const float4*)&A[(size_t)grow_l * IN_C];
    bool inM = (grow_l < M);

    for (int chunk = 0; chunk < 8; chunk++) {
        // load A chunk (128 x 32 fp16)
        {
            float4 v[4];
#pragma unroll
            for (int i = 0; i < 4; i++)
                v[i] = inM ? arow[(chunk * 32 + lc) / 4 + i] : make_float4(0.f, 0.f, 0.f, 0.f);
            uint4 s0, s1;
            {
                __half2 h0 = __floats2half2_rn(v[0].x, v[0].y);
                __half2 h1 = __floats2half2_rn(v[0].z, v[0].w);
                __half2 h2 = __floats2half2_rn(v[1].x, v[1].y);
                __half2 h3 = __floats2half2_rn(v[1].z, v[1].w);
                s0 = make_uint4(*(uint32_t*)&h0, *(uint32_t*)&h1, *(uint32_t*)&h2, *(uint32_t*)&h3);
                __half2 h4 = __floats2half2_rn(v[2].x, v[2].y);
                __half2 h5 = __floats2half2_rn(v[2].z, v[2].w);
                __half2 h6 = __floats2half2_rn(v[3].x, v[3].y);
                __half2 h7 = __floats2half2_rn(v[3].z, v[3].w);
                s1 = make_uint4(*(uint32_t*)&h4, *(uint32_t*)&h5, *(uint32_t*)&h6, *(uint32_t*)&h7);
            }
            *(uint4*)&As[lr][lc]     = s0;
            *(uint4*)&As[lr][lc + 8] = s1;
        }
        __syncthreads();

#pragma unroll
        for (int s = 0; s < 2; s++) {
            int ks = chunk * 2 + s;
            // B fragments: one coalesced LDG.64 per n-tile (L2-resident)
            uint2 bf[4];
            const uint2* bp = &g_Bfrag[(ks * 16 + warp_n * 4) * 32 + lane];
#pragma unroll
            for (int nt = 0; nt < 4; nt++) bf[nt] = bp[nt * 32];
            // A fragments: ldmatrix x4 per m-tile
            uint32_t af[4][4];
#pragma unroll
            for (int mt = 0; mt < 4; mt++) {
                uint32_t addr = aBase + ((uint32_t)(mt * 16 * ASTRIDE + s * 16) << 1);
                asm volatile(
                    "ldmatrix.sync.aligned.m8n8.x4.shared.b16 {%0,%1,%2,%3}, [%4];"
                    : "=r"(af[mt][0]), "=r"(af[mt][1]), "=r"(af[mt][2]), "=r"(af[mt][3])
                    : "r"(addr));
            }
#pragma unroll
            for (int mt = 0; mt < 4; mt++)
#pragma unroll
                for (int nt = 0; nt < 4; nt++)
                    asm volatile(
                        "mma.sync.aligned.m16n8k16.row.col.f32.f16.f16.f32 "
                        "{%0,%1,%2,%3}, {%4,%5,%6,%7}, {%8,%9}, {%0,%1,%2,%3};"
                        : "+f"(acc[mt][nt][0]), "+f"(acc[mt][nt][1]),
                          "+f"(acc[mt][nt][2]), "+f"(acc[mt][nt][3])
                        : "r"(af[mt][0]), "r"(af[mt][1]), "r"(af[mt][2]), "r"(af[mt][3]),
                          "r"(bf[nt].x), "r"(bf[nt].y));
        }
        __syncthreads();
    }

    // epilogue: store fp16. lane l holds rows (l>>2, l>>2+8), cols (l&3)*2,+1 per (mt,nt)
    int r0 = lane >> 2;
    int cq = (lane & 3) * 2;
#pragma unroll
    for (int mt = 0; mt < 4; mt++) {
        int grow0 = bm + warp_m * 64 + mt * 16 + r0;
        int grow1 = grow0 + 8;
#pragma unroll
        for (int nt = 0; nt < 4; nt++) {
            int col = warp_n * 32 + nt * 8 + cq;
            if (grow0 < M) {
                __half2 h = __floats2half2_rn(acc[mt][nt][0], acc[mt][nt][1]);
                *(__half2*)&g_h1h[(size_t)grow0 * HID_C + col] = h;
            }
            if (grow1 < M) {
                __half2 h = __floats2half2_rn(acc[mt][nt][2], acc[mt][nt][3]);
                *(__half2*)&g_h1h[(size_t)grow1 * HID_C + col] = h;
            }
        }
    }
}

// ---------------- attention coefficients from fp16 h1 ----------------
__global__ void attn1h_kernel(const float* __restrict__ att_src,
                              const float* __restrict__ att_dst, int N) {
    int idx = blockIdx.x * blockDim.x + threadIdx.x;  // n*8 + h
    if (idx >= N * HEADS) return;
    int h = idx & 7;
    int n = idx >> 3;
    const uint4* hp = (const uint4*)&g_h1h[(size_t)n * HID_C + h * 16];
    uint4 r0 = hp[0], r1 = hp[1];
    uint32_t raw[8] = {r0.x, r0.y, r0.z, r0.w, r1.x, r1.y, r1.z, r1.w};
    float ss = 0.f, sd = 0.f;
#pragma unroll
    for (int j = 0; j < 8; j++) {
        float2 f = __half22float2(*(__half2*)&raw[j]);
        ss = fmaf(f.x, att_src[h * 16 + 2 * j], ss);
        ss = fmaf(f.y, att_src[h * 16 + 2 * j + 1], ss);
        sd = fmaf(f.x, att_dst[h * 16 + 2 * j], sd);
        sd = fmaf(f.y, att_dst[h * 16 + 2 * j + 1], sd);
    }
    g_asrc1[idx] = ss;
    g_adst1[idx] = sd;
}

// ---------------- CSR build (4 edges / thread) ----------------
__global__ void count_kernel(const int* __restrict__ dst, int E) {
    int base = (blockIdx.x * blockDim.x + threadIdx.x) * 4;
    if (base + 3 < E) {
        int4 d = *(const int4*)&dst[base];
        atomicAdd(&g_deg[d.x], 1);
        atomicAdd(&g_deg[d.y], 1);
        atomicAdd(&g_deg[d.z], 1);
        atomicAdd(&g_deg[d.w], 1);
    } else {
        for (int e = base; e < E; e++) atomicAdd(&g_deg[dst[e]], 1);
    }
}

#define SCAN_CH 52    // 52 * 1024 = N_PAD
__global__ __launch_bounds__(1024) void scan_kernel(int N) {
    __shared__ int sums[1024];
    int t = threadIdx.x;
    int base = t * SCAN_CH;
    int4 buf[SCAN_CH / 4];
#pragma unroll
    for (int i = 0; i < SCAN_CH / 4; i++) buf[i] = *(const int4*)&g_deg[base + i * 4];
    int s = 0;
#pragma unroll
    for (int i = 0; i < SCAN_CH / 4; i++) s += buf[i].x + buf[i].y + buf[i].z + buf[i].w;
    sums[t] = s;
    __syncthreads();
    for (int off = 1; off < 1024; off <<= 1) {
        int v = (t >= off) ? sums[t - off] : 0;
        __syncthreads();
        if (t >= off) sums[t] += v;
        __syncthreads();
    }
    int run = (t == 0) ? 0 : sums[t - 1];
#pragma unroll
    for (int i = 0; i < SCAN_CH / 4; i++) {
        int4 d = buf[i];
        int4 rp;
        rp.x = run; run += d.x;
        rp.y = run; run += d.y;
        rp.z = run; run += d.z;
        rp.w = run; run += d.w;
        *(int4*)&g_rowptr[base + i * 4] = rp;
        *(int4*)&g_cursor[base + i * 4] = rp;
    }
    if (t == 1023) g_rowptr[N_PAD] = sums[1023];
}

__global__ void scatter_kernel(const int* __restrict__ src, const int* __restrict__ dst, int E) {
    int base = (blockIdx.x * blockDim.x + threadIdx.x) * 4;
    if (base + 3 < E) {
        int4 d = *(const int4*)&dst[base];
        int4 sv = *(const int4*)&src[base];
        int p0 = atomicAdd(&g_cursor[d.x], 1);
        int p1 = atomicAdd(&g_cursor[d.y], 1);
        int p2 = atomicAdd(&g_cursor[d.z], 1);
        int p3 = atomicAdd(&g_cursor[d.w], 1);
        g_adj[p0] = sv.x;
        g_adj[p1] = sv.y;
        g_adj[p2] = sv.z;
        g_adj[p3] = sv.w;
    } else {
        for (int e = base; e < E; e++) {
            int pos = atomicAdd(&g_cursor[dst[e]], 1);
            g_adj[pos] = src[e];
        }
    }
}

// ---------------- layer-1 aggregation: warp per node, fp16 gather ----------------
__global__ __launch_bounds__(256) void agg1_kernel(const float* __restrict__ bias1, int N) {
    int gw = (blockIdx.x * blockDim.x + threadIdx.x) >> 5;
    if (gw >= N) return;
    int lane = threadIdx.x & 31;
    int head = lane >> 2;
    int c0 = lane * 4;

    float adst = g_adst1[gw * HEADS + head];

    float p0 = __expf(leaky(g_asrc1[gw * HEADS + head] + adst));
    float s = p0;
    float4 acc;
    {
        uint2 hraw = *(const uint2*)&g_h1h[(size_t)gw * HID_C + c0];
        float2 f01 = __half22float2(*(__half2*)&hraw.x);
        float2 f23 = __half22float2(*(__half2*)&hraw.y);
        acc = make_float4(p0 * f01.x, p0 * f01.y, p0 * f23.x, p0 * f23.y);
    }

    int beg = g_rowptr[gw];
    int end = g_rowptr[gw + 1];
#pragma unroll 4
    for (int e = beg; e < end; e++) {
        int src = g_adj[e];
        float t = g_asrc1[src * HEADS + head];
        uint2 hraw = *(const uint2*)&g_h1h[(size_t)src * HID_C + c0];
        float p = __expf(leaky(t + adst));
        float2 f01 = __half22float2(*(__half2*)&hraw.x);
        float2 f23 = __half22float2(*(__half2*)&hraw.y);
        s += p;
        acc.x = fmaf(p, f01.x, acc.x);
        acc.y = fmaf(p, f01.y, acc.y);
        acc.z = fmaf(p, f23.x, acc.z);
        acc.w = fmaf(p, f23.y, acc.w);
    }
    float inv = 1.f / s;
    float4 o;
    o.x = fmaxf(fmaf(acc.x, inv, bias1[c0 + 0]), 0.f);
    o.y = fmaxf(fmaf(acc.y, inv, bias1[c0 + 1]), 0.f);
    o.z = fmaxf(fmaf(acc.z, inv, bias1[c0 + 2]), 0.f);
    o.w = fmaxf(fmaf(acc.w, inv, bias1[c0 + 3]), 0.f);
    *(float4*)&g_h2[(size_t)gw * HID_C + c0] = o;
}

// ---------------- layer 2: g2 = h2 @ W2 (+ attention scores), fused, fp16 out ----------------
__global__ __launch_bounds__(256) void gemm2_kernel(const float* __restrict__ W2,
                                                    const float* __restrict__ att_src,
                                                    const float* __restrict__ att_dst, int N) {
    __shared__ float Ws[HID_C * OUT_C];
    __shared__ float Hs[16][HID_C];
    int tid = threadIdx.x;
    int nodeBase = blockIdx.x * 16;
    for (int i = tid; i < HID_C * OUT_C; i += 256) Ws[i] = W2[i];
    int lnode = tid >> 4;
    int seg = tid & 15;
    int gnode = nodeBase + lnode;
    if (gnode < N) {
        *(float4*)&Hs[lnode][seg * 8]     = *(const float4*)&g_h2[(size_t)gnode * HID_C + seg * 8];
        *(float4*)&Hs[lnode][seg * 8 + 4] = *(const float4*)&g_h2[(size_t)gnode * HID_C + seg * 8 + 4];
    }
    __syncthreads();
    int j = tid & 15;
    float acc = 0.f;
#pragma unroll 8
    for (int c = 0; c < HID_C; c++) acc = fmaf(Hs[lnode][c], Ws[c * OUT_C + j], acc);
    float vs = acc * att_src[j];
    float vd = acc * att_dst[j];
#pragma unroll
    for (int off = 8; off; off >>= 1) {
        vs += __shfl_down_sync(0xffffffffu, vs, off, 16);
        vd += __shfl_down_sync(0xffffffffu, vd, off, 16);
    }
    if (gnode < N) {
        g_g2h[gnode * OUT_C + j] = __float2half_rn(acc);
        if (j == 0) {
            g_asrc2[gnode] = vs;
            g_adst2[gnode] = vd;
        }
    }
}

// ---------------- layer-2 aggregation: 4 edge streams / warp, fp16 gather ----------------
__global__ __launch_bounds__(256) void agg2_kernel(const float* __restrict__ bias2,
                                                   float* __restrict__ out, int N) {
    int gw = (blockIdx.x * blockDim.x + threadIdx.x) >> 5;
    if (gw >= N) return;
    int lane = threadIdx.x & 31;
    int grp = lane >> 3;        // 4 groups of 8 lanes
    int cp = lane & 7;          // channel pair: channels 2cp, 2cp+1

    float adst = g_adst2[gw];
    int beg = g_rowptr[gw];
    int end = g_rowptr[gw + 1];

    float s = 0.f, ax = 0.f, ay = 0.f;
    if (grp == 0) {  // self loop
        float p0 = __expf(leaky(g_asrc2[gw] + adst));
        float2 f = __half22float2(*(const __half2*)&g_g2h[gw * OUT_C + cp * 2]);
        s = p0;
        ax = p0 * f.x;
        ay = p0 * f.y;
    }
#pragma unroll 2
    for (int e = beg + grp; e < end; e += 4) {
        int src = g_adj[e];
        float p = __expf(leaky(g_asrc2[src] + adst));
        float2 f = __half22float2(*(const __half2*)&g_g2h[src * OUT_C + cp * 2]);
        s += p;
        ax = fmaf(p, f.x, ax);
        ay = fmaf(p, f.y, ay);
    }
    s  += __shfl_xor_sync(0xffffffffu, s, 8);
    ax += __shfl_xor_sync(0xffffffffu, ax, 8);
    ay += __shfl_xor_sync(0xffffffffu, ay, 8);
    s  += __shfl_xor_sync(0xffffffffu, s, 16);
    ax += __shfl_xor_sync(0xffffffffu, ax, 16);
    ay += __shfl_xor_sync(0xffffffffu, ay, 16);
    if (grp == 0) {
        float inv = 1.f / s;
        float2 o = make_float2(ax * inv + bias2[cp * 2], ay * inv + bias2[cp * 2 + 1]);
        *(float2*)&out[gw * OUT_C + cp * 2] = o;
    }
}

// ---------------- launch: fork-join graph (CSR build || Bfrag-prep -> GEMM1 -> attn1h) ----------------
extern "C" void kernel_launch(void* const* d_in, const int* in_sizes, int n_in,
                              void* d_out, int out_size) {
    const float* x        = (const float*)d_in[0];
    const int*   eidx     = (const int*)d_in[1];
    const float* W1       = (const float*)d_in[2];
    const float* att_src1 = (const float*)d_in[3];
    const float* att_dst1 = (const float*)d_in[4];
    const float* bias1    = (const float*)d_in[5];
    const float* W2       = (const float*)d_in[6];
    const float* att_src2 = (const float*)d_in[7];
    const float* att_dst2 = (const float*)d_in[8];
    const float* bias2    = (const float*)d_in[9];
    float* out = (float*)d_out;

    int N = in_sizes[0] / IN_C;
    int E = in_sizes[1] / 2;
    const int* srcArr = eidx;
    const int* dstArr = eidx + E;

    static cudaStream_t s2 = nullptr;
    static cudaEvent_t evFork = nullptr, evJoin = nullptr;
    static void* degPtr = nullptr;
    if (!s2) {
        cudaStreamCreateWithFlags(&s2, cudaStreamNonBlocking);
        cudaEventCreateWithFlags(&evFork, cudaEventDisableTiming);
        cudaEventCreateWithFlags(&evJoin, cudaEventDisableTiming);
        cudaGetSymbolAddress(&degPtr, g_deg);
    }

    // fork: CSR build on side stream
    cudaEventRecord(evFork, 0);
    cudaStreamWaitEvent(s2, evFork, 0);
    cudaMemsetAsync(degPtr, 0, N_PAD * sizeof(int), s2);
    count_kernel<<<(E / 4 + 255) / 256, 256, 0, s2>>>(dstArr, E);
    scan_kernel<<<1, 1024, 0, s2>>>(N);
    scatter_kernel<<<(E / 4 + 255) / 256, 256, 0, s2>>>(srcArr, dstArr, E);
    cudaEventRecord(evJoin, s2);

    // main stream: B fragments, tensor-core GEMM1, attention coefficients
    prep_bfrag_kernel<<<32, 256>>>(W1);
    gemm1_mma_kernel<<<(N + 127) / 128, 256>>>(x, N);
    attn1h_kernel<<<(N * HEADS + 255) / 256, 256>>>(att_src1, att_dst1, N);

    // join
    cudaStreamWaitEvent(0, evJoin, 0);

    agg1_kernel<<<(N * 32 + 255) / 256, 256>>>(bias1, N);
    gemm2_kernel<<<(N + 15) / 16, 256>>>(W2, att_src2, att_dst2, N);
    agg2_kernel<<<(N * 32 + 255) / 256, 256>>>(bias2, out, N);
}